// round 14
// baseline (speedup 1.0000x reference)
#include <cuda_runtime.h>
#include <cuda_fp16.h>
#include <cstdint>

#define NN 20000
#define KNB 32
#define DD 128
#define GT 4096
#define PAIRS 4            // node-pairs per K2 CTA

// ---------------- device scratch (no runtime allocation) --------------------
__device__ float g_gate_table[GT + 1];
__device__ __align__(16) __half g_Wh[128 * 144];  // fp16 W image, [n][k-interleaved], 288B rows
__device__ __align__(16) float g_u[DD];           // W @ phi_n
__device__ __align__(16) float g_v[DD];           // W @ phi_s
__device__ float g_c0, g_c1;                      // b.phi_n, b.phi_s

// ---------------- fused K2 smem layout (float offsets) -----------------------
#define W_O    0            // 9216 floats = 36864 B fp16 W image
#define PN_O   9216         // 8 warps x 256 partials
#define SC_O   11264        // 64 raw scores
#define SSP_O  11328        // 8 per-warp s_self partials
#define ATT_O  11336        // 64 att*gate
#define ZS_O   11400        // 8 x 132 z tile
#define BIAS_O 12456        // 128
#define BETA_O 12584        // 8
#define K2_FLOATS 12592
#define K2_SMEM (K2_FLOATS * 4)

// ---------------- helpers ----------------------------------------------------
__device__ __forceinline__ void mma16(float* c, const uint32_t* a, uint32_t b0, uint32_t b1) {
    asm volatile(
        "mma.sync.aligned.m16n8k16.row.col.f32.f16.f16.f32 "
        "{%0,%1,%2,%3}, {%4,%5,%6,%7}, {%8,%9}, {%0,%1,%2,%3};\n"
        : "+f"(c[0]), "+f"(c[1]), "+f"(c[2]), "+f"(c[3])
        : "r"(a[0]), "r"(a[1]), "r"(a[2]), "r"(a[3]), "r"(b0), "r"(b1));
}
__device__ __forceinline__ uint32_t pack2(float lo, float hi) {
    __half2 h = __floats2half2_rn(lo, hi);
    return *(uint32_t*)&h;
}

// ---------------- K1: init — one wave ----------------------------------------
// blocks 0..128: gate table (warp does 4 entries); 129..144: W image; 145: u/v/c
__global__ void __launch_bounds__(256) init_kernel(
    const float* __restrict__ w1, const float* __restrict__ b1,
    const float* __restrict__ w2, const float* __restrict__ b2,
    const float* __restrict__ W, const float* __restrict__ bias,
    const float* __restrict__ phi)
{
    const int t = threadIdx.x, lane = t & 31, w = t >> 5;
    const int bx = blockIdx.x;

    if (bx <= 128) {
        const float w1l = w1[lane], w2l = w2[lane];
        const float b1v = b1[0], b2v = b2[0];
        #pragma unroll
        for (int e = 0; e < 4; e++) {
            const int gw = (bx * 8 + w) * 4 + e;
            if (gw <= GT) {
                float d = (float)gw * (64.0f / (float)GT);
                float s = 1.0f / (1.0f + __expf(-(d * w1l + b1v)));
                float p = s * w2l;
                #pragma unroll
                for (int off = 16; off; off >>= 1)
                    p += __shfl_xor_sync(0xffffffffu, p, off);
                if (lane == 0)
                    g_gate_table[gw] = 1.0f / (1.0f + __expf(-(p + b2v)));
            }
        }
    } else if (bx <= 144) {
        const int gid2 = (bx - 129) * 256 + t;
        {
            int n = gid2 >> 5, c = (gid2 >> 2) & 7, q = gid2 & 3;
            int k0 = c * 16 + q * 2;
            __half2 h0 = __floats2half2_rn(W[k0 * DD + n],       W[(k0 + 1) * DD + n]);
            __half2 h1 = __floats2half2_rn(W[(k0 + 8) * DD + n], W[(k0 + 9) * DD + n]);
            *(__half2*)(g_Wh + n * 144 + c * 16 + q * 4)     = h0;
            *(__half2*)(g_Wh + n * 144 + c * 16 + q * 4 + 2) = h1;
        }
        if (gid2 < 1024) {
            int n = gid2 >> 3, j = gid2 & 7;
            *(uint32_t*)(g_Wh + n * 144 + 128 + j * 2) = 0;
        }
    } else {
        float pn0 = phi[lane], pn1 = phi[lane + 32], pn2 = phi[lane + 64], pn3 = phi[lane + 96];
        float ps0 = phi[DD + lane], ps1 = phi[DD + lane + 32];
        float ps2 = phi[DD + lane + 64], ps3 = phi[DD + lane + 96];
        #pragma unroll
        for (int rr = 0; rr < 16; rr++) {
            const int r = w * 16 + rr;
            float w0 = W[r * DD + lane],      w1v = W[r * DD + lane + 32];
            float w2v = W[r * DD + lane + 64], w3 = W[r * DD + lane + 96];
            float pu = w0 * pn0 + w1v * pn1 + w2v * pn2 + w3 * pn3;
            float pv = w0 * ps0 + w1v * ps1 + w2v * ps2 + w3 * ps3;
            #pragma unroll
            for (int off = 16; off; off >>= 1) {
                pu += __shfl_xor_sync(0xffffffffu, pu, off);
                pv += __shfl_xor_sync(0xffffffffu, pv, off);
            }
            if (lane == 0) { g_u[r] = pu; g_v[r] = pv; }
        }
        if (w < 2) {
            float b0 = bias[lane], b1v = bias[lane + 32];
            float b2v = bias[lane + 64], b3 = bias[lane + 96];
            float p = (w == 0)
                ? (b0 * pn0 + b1v * pn1 + b2v * pn2 + b3 * pn3)
                : (b0 * ps0 + b1v * ps1 + b2v * ps2 + b3 * ps3);
            #pragma unroll
            for (int off = 16; off; off >>= 1)
                p += __shfl_xor_sync(0xffffffffu, p, off);
            if (lane == 0) { if (w == 0) g_c0 = p; else g_c1 = p; }
        }
    }
}

// ---------------- K2: fully fused streaming kernel ---------------------------
// Register-direct attention (R13-proven) + per-CTA 8x128x128 fp16 mini-GEMM.
// NO cp.async anywhere (toolchain constraint, R8-R11 bisection).
__global__ void __launch_bounds__(256) stream_kernel(
    const float* __restrict__ x_self, const float* __restrict__ x_nb,
    const float* __restrict__ deg,
    const float* __restrict__ wsp, const float* __restrict__ wnp,
    const float* __restrict__ bias, float* __restrict__ out)
{
    extern __shared__ float smf[];
    const int t = threadIdx.x, lane = t & 31, w = t >> 5;
    const int pair0 = blockIdx.x * PAIRS;
    const int node_t = t >> 7, col_t = t & 127;

    const float4 u4 = *(const float4*)(g_u + lane * 4);
    const float vv = g_v[col_t];
    const float wsv = wsp[0], wnv = wnp[0];
    const float c0 = g_c0, c1 = g_c1;

    if (t < 128) smf[BIAS_O + t] = bias[t];

    float4 rx[2][8];
    float rxs[2], rdg[2];

    // prologue: tile 0 -> buffer 0
    {
        const float4* Ab4 = (const float4*)(x_nb + (size_t)pair0 * 2 * KNB * DD);
        #pragma unroll
        for (int i = 0; i < 8; i++)
            rx[0][i] = Ab4[(w + 8 * i) * 32 + lane];
        rxs[0] = x_self[(size_t)(pair0 * 2 + node_t) * DD + col_t];
        rdg[0] = (w < 2) ? deg[(size_t)pair0 * 2 * KNB + w * 32 + lane] : 0.f;
    }

    #pragma unroll
    for (int it = 0; it < PAIRS; it++) {
        const int cb = it & 1, nb = cb ^ 1;
        const int node0 = (pair0 + it) * 2;

        // prefetch next tile into the other register buffer
        if (it + 1 < PAIRS) {
            const float4* Ab4 = (const float4*)(x_nb + (size_t)(node0 + 2) * KNB * DD);
            #pragma unroll
            for (int i = 0; i < 8; i++)
                rx[nb][i] = Ab4[(w + 8 * i) * 32 + lane];
            rxs[nb] = x_self[(size_t)(node0 + 2 + node_t) * DD + col_t];
            rdg[nb] = (w < 2) ? deg[(size_t)(node0 + 2) * KNB + w * 32 + lane] : 0.f;
        }
        // W image chunk loads (3 float4/thread on iterations 0..2; stored late)
        float4 wr0, wr1, wr2;
        if (it < 3) {
            const float4* Wg4 = (const float4*)g_Wh;
            wr0 = Wg4[it * 768 + t];
            wr1 = Wg4[it * 768 + 256 + t];
            wr2 = Wg4[it * 768 + 512 + t];
        }

        // ---- score partials from registers ----
        float v[8];
        #pragma unroll
        for (int i = 0; i < 8; i++) {
            float4 x = rx[cb][i];
            v[i] = x.x * u4.x + x.y * u4.y + x.z * u4.z + x.w * u4.w;
        }
        #pragma unroll
        for (int j = 0; j < 4; j++) {
            float give = (lane & 16) ? v[j] : v[j + 4];
            float keep = (lane & 16) ? v[j + 4] : v[j];
            v[j] = keep + __shfl_xor_sync(0xffffffffu, give, 16);
        }
        #pragma unroll
        for (int j = 0; j < 2; j++) {
            float give = (lane & 8) ? v[j] : v[j + 2];
            float keep = (lane & 8) ? v[j + 2] : v[j];
            v[j] = keep + __shfl_xor_sync(0xffffffffu, give, 8);
        }
        {
            float give = (lane & 4) ? v[0] : v[1];
            float keep = (lane & 4) ? v[1] : v[0];
            v[0] = keep + __shfl_xor_sync(0xffffffffu, give, 4);
        }
        v[0] += __shfl_xor_sync(0xffffffffu, v[0], 2);
        v[0] += __shfl_xor_sync(0xffffffffu, v[0], 1);
        if ((lane & 3) == 0) smf[SC_O + w + 8 * (lane >> 2)] = v[0];

        // ---- s_self partial ----
        {
            float p = rxs[cb] * vv;
            #pragma unroll
            for (int off = 16; off; off >>= 1)
                p += __shfl_xor_sync(0xffffffffu, p, off);
            if (lane == 0) smf[SSP_O + w] = p;
        }
        __syncthreads();

        // ---- leaky + softmax + gate (warp per node) ----
        if (w < 2) {
            float ssl = smf[SSP_O + w * 4] + smf[SSP_O + w * 4 + 1]
                      + smf[SSP_O + w * 4 + 2] + smf[SSP_O + w * 4 + 3];
            float s = smf[SC_O + w * 32 + lane] + c0 + ssl + c1;
            s = (s > 0.f) ? s : 0.2f * s;
            float m = s;
            #pragma unroll
            for (int off = 16; off; off >>= 1)
                m = fmaxf(m, __shfl_xor_sync(0xffffffffu, m, off));
            float e = __expf(s - m);
            float ss = e;
            #pragma unroll
            for (int off = 16; off; off >>= 1)
                ss += __shfl_xor_sync(0xffffffffu, ss, off);
            float u = fminf(fmaxf(rdg[cb] * ((float)GT / 64.0f), 0.0f), (float)GT - 0.001f);
            int ix = (int)u; float fr = u - (float)ix;
            float g0 = g_gate_table[ix];
            float gt = g0 + (g_gate_table[ix + 1] - g0) * fr;
            float a = (e / ss) * gt;
            smf[ATT_O + w * 32 + lane] = a;
            float gs = a;
            #pragma unroll
            for (int off = 16; off; off >>= 1)
                gs += __shfl_xor_sync(0xffffffffu, gs, off);
            if (lane == 0) smf[BETA_O + it * 2 + w] = wsv + wnv * gs;
        }
        __syncthreads();

        // ---- weighted-sum partials from registers ----
        {
            float4 pn0 = make_float4(0.f, 0.f, 0.f, 0.f);
            float4 pn1 = make_float4(0.f, 0.f, 0.f, 0.f);
            #pragma unroll
            for (int i = 0; i < 4; i++) {
                float a = smf[ATT_O + w + 8 * i];
                float4 x = rx[cb][i];
                pn0.x += a * x.x; pn0.y += a * x.y; pn0.z += a * x.z; pn0.w += a * x.w;
            }
            #pragma unroll
            for (int i = 4; i < 8; i++) {
                float a = smf[ATT_O + w + 8 * i];
                float4 x = rx[cb][i];
                pn1.x += a * x.x; pn1.y += a * x.y; pn1.z += a * x.z; pn1.w += a * x.w;
            }
            *(float4*)(smf + PN_O + (w * 64 + lane) * 4)      = pn0;
            *(float4*)(smf + PN_O + (w * 64 + 32 + lane) * 4) = pn1;
        }
        // store W chunk (loads issued at top; long separation hides latency)
        if (it < 3) {
            float4* Ws4 = (float4*)(smf + W_O);
            Ws4[it * 768 + t]       = wr0;
            Ws4[it * 768 + 256 + t] = wr1;
            Ws4[it * 768 + 512 + t] = wr2;
        }
        __syncthreads();

        // ---- final: z row into smem tile ----
        {
            float y = 0.f;
            #pragma unroll
            for (int ww = 0; ww < 8; ww++)
                y += smf[PN_O + ww * 256 + node_t * 128 + col_t];
            smf[ZS_O + (it * 2 + node_t) * 132 + col_t] = wsv * rxs[cb] + wnv * y;
        }
    }
    __syncthreads();   // z tile, W image, beta, bias all resident

    // ---- fused mini-GEMM: out[8 rows] = relu(z @ W + beta*bias) ----
    {
        const int lr = lane >> 2, q2 = (lane & 3) * 2;
        const char* Wb = (const char*)(smf + W_O);
        float acc[2][4] = {};
        #pragma unroll
        for (int kc8 = 0; kc8 < 8; kc8++) {
            const int kk = kc8 * 16;
            float2 za = *(const float2*)(smf + ZS_O + lr * 132 + kk + q2);
            float2 zb = *(const float2*)(smf + ZS_O + lr * 132 + kk + q2 + 8);
            uint32_t a[4];
            a[0] = pack2(za.x, za.y);
            a[1] = 0u;
            a[2] = pack2(zb.x, zb.y);
            a[3] = 0u;
            #pragma unroll
            for (int nt = 0; nt < 2; nt++) {
                const int n = w * 16 + nt * 8 + lr;
                uint2 b = *(const uint2*)(Wb + n * 288 + kc8 * 32 + q2 * 4);
                mma16(acc[nt], a, b.x, b.y);
            }
        }
        const float be = smf[BETA_O + lr];
        const size_t gr = (size_t)(pair0 * 2 + lr) * DD;
        #pragma unroll
        for (int nt = 0; nt < 2; nt++) {
            const int cc = w * 16 + nt * 8 + q2;
            float o0 = acc[nt][0] + be * smf[BIAS_O + cc];
            float o1 = acc[nt][1] + be * smf[BIAS_O + cc + 1];
            o0 = (o0 > 0.f) ? o0 : 0.f;
            o1 = (o1 > 0.f) ? o1 : 0.f;
            *(float2*)(out + gr + cc) = make_float2(o0, o1);
        }
    }
}

// ---------------- launch -----------------------------------------------------
extern "C" void kernel_launch(void* const* d_in, const int* in_sizes, int n_in,
                              void* d_out, int out_size)
{
    const float* x_self = (const float*)d_in[0];
    const float* x_nb   = (const float*)d_in[1];
    const float* deg    = (const float*)d_in[2];
    const float* W      = (const float*)d_in[3];
    const float* bias   = (const float*)d_in[4];
    const float* phi    = (const float*)d_in[5];
    const float* w1     = (const float*)d_in[6];
    const float* b1     = (const float*)d_in[7];
    const float* w2     = (const float*)d_in[8];
    const float* b2     = (const float*)d_in[9];
    const float* wsp    = (const float*)d_in[10];
    const float* wnp    = (const float*)d_in[11];
    float* out = (float*)d_out;

    cudaFuncSetAttribute(stream_kernel, cudaFuncAttributeMaxDynamicSharedMemorySize, K2_SMEM);

    init_kernel<<<146, 256>>>(w1, b1, w2, b2, W, bias, phi);
    stream_kernel<<<NN / (2 * PAIRS), 256, K2_SMEM>>>(x_self, x_nb, deg, wsp, wnp, bias, out);
}

// round 15
// speedup vs baseline: 1.1070x; 1.1070x over previous
#include <cuda_runtime.h>
#include <cuda_fp16.h>
#include <cstdint>

#define NN 20000
#define KNB 32
#define DD 128
#define GT 4096
#define PAIRS 4            // node-pairs per K2 CTA

// ---------------- device scratch (no runtime allocation) --------------------
__device__ float g_gate_table[GT + 1];
__device__ __align__(16) __half g_Wh[128 * 144];  // fp16 W image, [n][k-interleaved], 288B rows
__device__ __align__(16) float g_u[DD];           // W @ phi_n
__device__ __align__(16) float g_v[DD];           // W @ phi_s
__device__ float g_c0, g_c1;                      // b.phi_n, b.phi_s
__device__ __align__(16) float g_z[NN * DD];      // ws*x_self + wn*y
__device__ float g_beta[NN];                      // ws + wn*gs

// ---------------- K3 smem layout (bytes) — proven R6-R13 GEMM ---------------
#define A_STRIDE_F 40
#define A_BUF_B   20480
#define W_OFF_B   40960
#define EP_OFF_B  77824
#define SMEM_TOTAL 83008

// ---------------- K2 static smem (float offsets) -----------------------------
#define PN_O   0            // 8 warps x 2 nodes x 32 lanes x float4 = 2048
#define SC_O   2048         // 64 raw scores
#define SSP_O  2112         // 8 per-warp s_self partials
#define ATT_O  2120         // 64 att*gate
#define K2_FLOATS 2184

// ---------------- helpers ----------------------------------------------------
__device__ __forceinline__ uint32_t s2u(const void* p) {
    return (uint32_t)__cvta_generic_to_shared(p);
}
__device__ __forceinline__ void cp16p(uint32_t sa, const float* g, bool v) {
    int sz = v ? 16 : 0;
    asm volatile("cp.async.cg.shared.global [%0], [%1], 16, %2;" :: "r"(sa), "l"(g), "r"(sz));
}
#define CP_COMMIT() asm volatile("cp.async.commit_group;" ::: "memory")
#define CP_WAIT1()  asm volatile("cp.async.wait_group 1;" ::: "memory")
#define CP_WAIT0()  asm volatile("cp.async.wait_group 0;" ::: "memory")

__device__ __forceinline__ void mma16(float* c, const uint32_t* a, uint32_t b0, uint32_t b1) {
    asm volatile(
        "mma.sync.aligned.m16n8k16.row.col.f32.f16.f16.f32 "
        "{%0,%1,%2,%3}, {%4,%5,%6,%7}, {%8,%9}, {%0,%1,%2,%3};\n"
        : "+f"(c[0]), "+f"(c[1]), "+f"(c[2]), "+f"(c[3])
        : "r"(a[0]), "r"(a[1]), "r"(a[2]), "r"(a[3]), "r"(b0), "r"(b1));
}
__device__ __forceinline__ uint32_t pack2(float lo, float hi) {
    __half2 h = __floats2half2_rn(lo, hi);
    return *(uint32_t*)&h;
}

// ---------------- K3 GEMM machinery (proven R6-R13) --------------------------
__device__ __forceinline__ void stageA(uint32_t smem_base, int buf,
                                       const float* __restrict__ Ag, int valid) {
    const int t = threadIdx.x;
    const uint32_t base = smem_base + buf * A_BUF_B;
    #pragma unroll
    for (int i = 0; i < 4; i++) {
        int e = t + i * 256;
        int row = e >> 3, c4 = (e & 7) << 2;
        cp16p(base + row * 160 + c4 * 4, Ag + row * DD + c4, row < valid);
    }
}

__device__ __forceinline__ void compute_chunk(
    const float* __restrict__ As, const char* __restrict__ Wb, int kc,
    float (&acc)[2][8][4], int wm, int wn, int lane)
{
    const int q2 = (lane & 3) * 2;
    const int lr = lane >> 2;
    const int r0 = wm * 32 + lr;
    #pragma unroll
    for (int s = 0; s < 2; s++) {
        const int kk = s * 16;
        float2 A00 = *(const float2*)(As + (r0     ) * A_STRIDE_F + kk + q2);
        float2 A01 = *(const float2*)(As + (r0 +  8) * A_STRIDE_F + kk + q2);
        float2 A02 = *(const float2*)(As + (r0     ) * A_STRIDE_F + kk + q2 + 8);
        float2 A03 = *(const float2*)(As + (r0 +  8) * A_STRIDE_F + kk + q2 + 8);
        float2 A10 = *(const float2*)(As + (r0 + 16) * A_STRIDE_F + kk + q2);
        float2 A11 = *(const float2*)(As + (r0 + 24) * A_STRIDE_F + kk + q2);
        float2 A12 = *(const float2*)(As + (r0 + 16) * A_STRIDE_F + kk + q2 + 8);
        float2 A13 = *(const float2*)(As + (r0 + 24) * A_STRIDE_F + kk + q2 + 8);
        uint32_t a0[4], a1[4];
        a0[0] = pack2(A00.x, A00.y); a0[1] = pack2(A01.x, A01.y);
        a0[2] = pack2(A02.x, A02.y); a0[3] = pack2(A03.x, A03.y);
        a1[0] = pack2(A10.x, A10.y); a1[1] = pack2(A11.x, A11.y);
        a1[2] = pack2(A12.x, A12.y); a1[3] = pack2(A13.x, A13.y);
        const int coff = (kc * 2 + s) * 32 + q2 * 4;
        #pragma unroll
        for (int nt = 0; nt < 8; nt++) {
            const int n = wn * 64 + nt * 8 + lr;
            uint2 b = *(const uint2*)(Wb + n * 288 + coff);
            mma16(acc[0][nt], a0, b.x, b.y);
            mma16(acc[1][nt], a1, b.x, b.y);
        }
    }
}

__device__ __forceinline__ void gemm_pipe(
    char* smc, uint32_t smem_base, const float* __restrict__ Abase, int valid,
    float (&acc)[2][8][4], int wm, int wn, int lane)
{
    const int t = threadIdx.x;
    #pragma unroll
    for (int i = 0; i < 9; i++) {
        int e = t + i * 256;
        cp16p(smem_base + W_OFF_B + e * 16,
              (const float*)((const char*)g_Wh + e * 16), true);
    }
    stageA(smem_base, 0, Abase, valid);
    CP_COMMIT();

    const char* Wb = smc + W_OFF_B;
    #pragma unroll
    for (int kc = 0; kc < 4; kc++) {
        if (kc < 3) {
            stageA(smem_base, (kc + 1) & 1, Abase + (kc + 1) * 32, valid);
            CP_COMMIT();
            CP_WAIT1();
        } else {
            CP_WAIT0();
        }
        __syncthreads();
        compute_chunk((const float*)(smc + (kc & 1) * A_BUF_B), Wb, kc,
                      acc, wm, wn, lane);
        __syncthreads();
    }
}

// ---------------- K1: init — one wave ----------------------------------------
// blocks 0..128: gate table (warp does 4 entries); 129..144: W image; 145: u/v/c
__global__ void __launch_bounds__(256) init_kernel(
    const float* __restrict__ w1, const float* __restrict__ b1,
    const float* __restrict__ w2, const float* __restrict__ b2,
    const float* __restrict__ W, const float* __restrict__ bias,
    const float* __restrict__ phi)
{
    const int t = threadIdx.x, lane = t & 31, w = t >> 5;
    const int bx = blockIdx.x;

    if (bx <= 128) {
        const float w1l = w1[lane], w2l = w2[lane];
        const float b1v = b1[0], b2v = b2[0];
        #pragma unroll
        for (int e = 0; e < 4; e++) {
            const int gw = (bx * 8 + w) * 4 + e;
            if (gw <= GT) {
                float d = (float)gw * (64.0f / (float)GT);
                float s = 1.0f / (1.0f + __expf(-(d * w1l + b1v)));
                float p = s * w2l;
                #pragma unroll
                for (int off = 16; off; off >>= 1)
                    p += __shfl_xor_sync(0xffffffffu, p, off);
                if (lane == 0)
                    g_gate_table[gw] = 1.0f / (1.0f + __expf(-(p + b2v)));
            }
        }
    } else if (bx <= 144) {
        const int gid2 = (bx - 129) * 256 + t;
        {
            int n = gid2 >> 5, c = (gid2 >> 2) & 7, q = gid2 & 3;
            int k0 = c * 16 + q * 2;
            __half2 h0 = __floats2half2_rn(W[k0 * DD + n],       W[(k0 + 1) * DD + n]);
            __half2 h1 = __floats2half2_rn(W[(k0 + 8) * DD + n], W[(k0 + 9) * DD + n]);
            *(__half2*)(g_Wh + n * 144 + c * 16 + q * 4)     = h0;
            *(__half2*)(g_Wh + n * 144 + c * 16 + q * 4 + 2) = h1;
        }
        if (gid2 < 1024) {
            int n = gid2 >> 3, j = gid2 & 7;
            *(uint32_t*)(g_Wh + n * 144 + 128 + j * 2) = 0;
        }
    } else {
        float pn0 = phi[lane], pn1 = phi[lane + 32], pn2 = phi[lane + 64], pn3 = phi[lane + 96];
        float ps0 = phi[DD + lane], ps1 = phi[DD + lane + 32];
        float ps2 = phi[DD + lane + 64], ps3 = phi[DD + lane + 96];
        #pragma unroll
        for (int rr = 0; rr < 16; rr++) {
            const int r = w * 16 + rr;
            float w0 = W[r * DD + lane],      w1v = W[r * DD + lane + 32];
            float w2v = W[r * DD + lane + 64], w3 = W[r * DD + lane + 96];
            float pu = w0 * pn0 + w1v * pn1 + w2v * pn2 + w3 * pn3;
            float pv = w0 * ps0 + w1v * ps1 + w2v * ps2 + w3 * ps3;
            #pragma unroll
            for (int off = 16; off; off >>= 1) {
                pu += __shfl_xor_sync(0xffffffffu, pu, off);
                pv += __shfl_xor_sync(0xffffffffu, pv, off);
            }
            if (lane == 0) { g_u[r] = pu; g_v[r] = pv; }
        }
        if (w < 2) {
            float b0 = bias[lane], b1v = bias[lane + 32];
            float b2v = bias[lane + 64], b3 = bias[lane + 96];
            float p = (w == 0)
                ? (b0 * pn0 + b1v * pn1 + b2v * pn2 + b3 * pn3)
                : (b0 * ps0 + b1v * ps1 + b2v * ps2 + b3 * ps3);
            #pragma unroll
            for (int off = 16; off; off >>= 1)
                p += __shfl_xor_sync(0xffffffffu, p, off);
            if (lane == 0) { if (w == 0) g_c0 = p; else g_c1 = p; }
        }
    }
}

// ---------------- K2: register-direct streaming attention, 3 CTAs/SM ---------
// Split prefetch: rx[8] current tile, nx[4] first half of next; second half
// loaded into rx[4..7] after last use of current. NO cp.async (toolchain).
__global__ void __launch_bounds__(256, 3) stream_kernel(
    const float* __restrict__ x_self, const float* __restrict__ x_nb,
    const float* __restrict__ deg,
    const float* __restrict__ wsp, const float* __restrict__ wnp)
{
    __shared__ float smf[K2_FLOATS];
    const int t = threadIdx.x, lane = t & 31, w = t >> 5;
    const int pair0 = blockIdx.x * PAIRS;
    const int node_t = t >> 7, col_t = t & 127;

    const float4 u4 = *(const float4*)(g_u + lane * 4);
    const float vv = g_v[col_t];
    const float wsv = wsp[0], wnv = wnp[0];
    const float c0 = g_c0, c1 = g_c1;

    float4 rx[8], nx[4];
    float rxs_c, rxs_n = 0.f;

    // prologue: tile 0 full
    {
        const float4* Ab4 = (const float4*)(x_nb + (size_t)pair0 * 2 * KNB * DD);
        #pragma unroll
        for (int i = 0; i < 8; i++)
            rx[i] = Ab4[(w + 8 * i) * 32 + lane];
        rxs_c = x_self[(size_t)(pair0 * 2 + node_t) * DD + col_t];
    }

    #pragma unroll
    for (int it = 0; it < PAIRS; it++) {
        const int node0 = (pair0 + it) * 2;

        // current deg (softmax use; score phase covers latency)
        const float rdg = (w < 2) ? deg[(size_t)node0 * KNB + w * 32 + lane] : 0.f;

        // prefetch first half of next tile
        if (it + 1 < PAIRS) {
            const float4* Ab4 = (const float4*)(x_nb + (size_t)(node0 + 2) * KNB * DD);
            #pragma unroll
            for (int i = 0; i < 4; i++)
                nx[i] = Ab4[(w + 8 * i) * 32 + lane];
            rxs_n = x_self[(size_t)(node0 + 2 + node_t) * DD + col_t];
        }

        // ---- score partials from registers ----
        float v[8];
        #pragma unroll
        for (int i = 0; i < 8; i++) {
            float4 x = rx[i];
            v[i] = x.x * u4.x + x.y * u4.y + x.z * u4.z + x.w * u4.w;
        }
        #pragma unroll
        for (int j = 0; j < 4; j++) {
            float give = (lane & 16) ? v[j] : v[j + 4];
            float keep = (lane & 16) ? v[j + 4] : v[j];
            v[j] = keep + __shfl_xor_sync(0xffffffffu, give, 16);
        }
        #pragma unroll
        for (int j = 0; j < 2; j++) {
            float give = (lane & 8) ? v[j] : v[j + 2];
            float keep = (lane & 8) ? v[j + 2] : v[j];
            v[j] = keep + __shfl_xor_sync(0xffffffffu, give, 8);
        }
        {
            float give = (lane & 4) ? v[0] : v[1];
            float keep = (lane & 4) ? v[1] : v[0];
            v[0] = keep + __shfl_xor_sync(0xffffffffu, give, 4);
        }
        v[0] += __shfl_xor_sync(0xffffffffu, v[0], 2);
        v[0] += __shfl_xor_sync(0xffffffffu, v[0], 1);
        if ((lane & 3) == 0) smf[SC_O + w + 8 * (lane >> 2)] = v[0];

        // ---- s_self partial ----
        {
            float p = rxs_c * vv;
            #pragma unroll
            for (int off = 16; off; off >>= 1)
                p += __shfl_xor_sync(0xffffffffu, p, off);
            if (lane == 0) smf[SSP_O + w] = p;
        }
        __syncthreads();

        // ---- leaky + softmax + gate (warp per node) ----
        if (w < 2) {
            float ssl = smf[SSP_O + w * 4] + smf[SSP_O + w * 4 + 1]
                      + smf[SSP_O + w * 4 + 2] + smf[SSP_O + w * 4 + 3];
            float s = smf[SC_O + w * 32 + lane] + c0 + ssl + c1;
            s = (s > 0.f) ? s : 0.2f * s;
            float m = s;
            #pragma unroll
            for (int off = 16; off; off >>= 1)
                m = fmaxf(m, __shfl_xor_sync(0xffffffffu, m, off));
            float e = __expf(s - m);
            float ss = e;
            #pragma unroll
            for (int off = 16; off; off >>= 1)
                ss += __shfl_xor_sync(0xffffffffu, ss, off);
            float u = fminf(fmaxf(rdg * ((float)GT / 64.0f), 0.0f), (float)GT - 0.001f);
            int ix = (int)u; float fr = u - (float)ix;
            float g0 = g_gate_table[ix];
            float gt = g0 + (g_gate_table[ix + 1] - g0) * fr;
            float a = (e / ss) * gt;
            smf[ATT_O + w * 32 + lane] = a;
            float gs = a;
            #pragma unroll
            for (int off = 16; off; off >>= 1)
                gs += __shfl_xor_sync(0xffffffffu, gs, off);
            if (lane == 0) g_beta[node0 + w] = wsv + wnv * gs;
        }
        __syncthreads();

        // ---- weighted-sum partials from registers (att via broadcast LDS) ----
        {
            float4 pn0 = make_float4(0.f, 0.f, 0.f, 0.f);
            float4 pn1 = make_float4(0.f, 0.f, 0.f, 0.f);
            #pragma unroll
            for (int i = 0; i < 4; i++) {
                float a = smf[ATT_O + w + 8 * i];
                float4 x = rx[i];
                pn0.x += a * x.x; pn0.y += a * x.y; pn0.z += a * x.z; pn0.w += a * x.w;
            }
            #pragma unroll
            for (int i = 4; i < 8; i++) {
                float a = smf[ATT_O + w + 8 * i];
                float4 x = rx[i];
                pn1.x += a * x.x; pn1.y += a * x.y; pn1.z += a * x.z; pn1.w += a * x.w;
            }
            *(float4*)(smf + PN_O + (w * 64 + lane) * 4)      = pn0;
            *(float4*)(smf + PN_O + (w * 64 + 32 + lane) * 4) = pn1;
        }
        __syncthreads();

        // ---- final: sum 8 warp-partials, write z ----
        {
            float y = 0.f;
            #pragma unroll
            for (int ww = 0; ww < 8; ww++)
                y += smf[PN_O + ww * 256 + node_t * 128 + col_t];
            float z = wsv * rxs_c + wnv * y;
            g_z[(size_t)(node0 + node_t) * DD + col_t] = z;
        }

        // ---- rotate + second-half prefetch (covered by z write + next score) --
        if (it + 1 < PAIRS) {
            const float4* Ab4 = (const float4*)(x_nb + (size_t)(node0 + 2) * KNB * DD);
            rx[0] = nx[0]; rx[1] = nx[1]; rx[2] = nx[2]; rx[3] = nx[3];
            #pragma unroll
            for (int i = 4; i < 8; i++)
                rx[i] = Ab4[(w + 8 * i) * 32 + lane];
            rxs_c = rxs_n;
        }
        // barrier-free smem reuse proven in R13 (PN/SC/ATT write-read chains
        // separated by the three per-iteration barriers).
    }
}

// ---------------- K3: out = relu(z @ W + beta_n * b) -------------------------
__global__ void __launch_bounds__(256, 2) out_kernel(
    const float* __restrict__ bias, float* __restrict__ out)
{
    extern __shared__ char smc[];
    const uint32_t smem_base = s2u(smc);
    float* smf = (float*)(smc + EP_OFF_B);
    const int t = threadIdx.x, lane = t & 31, wid = t >> 5;
    const int wm = wid & 3, wn = wid >> 2, la = lane & 3, lr = lane >> 2;
    float* bias_s = smf;
    float* beta_s = smf + 128;

    const int row_base = blockIdx.x * 128;
    int valid = NN - row_base; if (valid > 128) valid = 128;

    if (t < 128) {
        bias_s[t] = bias[t];
        int gr = row_base + t;
        beta_s[t] = (gr < NN) ? g_beta[gr] : 0.f;
    }

    float acc[2][8][4] = {};
    gemm_pipe(smc, smem_base, g_z + (size_t)row_base * DD, valid, acc, wm, wn, lane);

    const int r = wm * 32 + lr;
    const float be0 = beta_s[r], be1 = beta_s[r + 8];
    const float be2 = beta_s[r + 16], be3 = beta_s[r + 24];
    #pragma unroll
    for (int nt = 0; nt < 8; nt++) {
        const int c = wn * 64 + nt * 8 + la * 2;
        const float b0 = bias_s[c], b1 = bias_s[c + 1];
        float o00 = acc[0][nt][0] + be0 * b0, o01 = acc[0][nt][1] + be0 * b1;
        float o10 = acc[0][nt][2] + be1 * b0, o11 = acc[0][nt][3] + be1 * b1;
        float o20 = acc[1][nt][0] + be2 * b0, o21 = acc[1][nt][1] + be2 * b1;
        float o30 = acc[1][nt][2] + be3 * b0, o31 = acc[1][nt][3] + be3 * b1;
        o00 = o00 > 0.f ? o00 : 0.f;  o01 = o01 > 0.f ? o01 : 0.f;
        o10 = o10 > 0.f ? o10 : 0.f;  o11 = o11 > 0.f ? o11 : 0.f;
        o20 = o20 > 0.f ? o20 : 0.f;  o21 = o21 > 0.f ? o21 : 0.f;
        o30 = o30 > 0.f ? o30 : 0.f;  o31 = o31 > 0.f ? o31 : 0.f;
        if (r      < valid) *(float2*)(out + (size_t)(row_base + r     ) * DD + c) = make_float2(o00, o01);
        if (r + 8  < valid) *(float2*)(out + (size_t)(row_base + r + 8 ) * DD + c) = make_float2(o10, o11);
        if (r + 16 < valid) *(float2*)(out + (size_t)(row_base + r + 16) * DD + c) = make_float2(o20, o21);
        if (r + 24 < valid) *(float2*)(out + (size_t)(row_base + r + 24) * DD + c) = make_float2(o30, o31);
    }
}

// ---------------- launch -----------------------------------------------------
extern "C" void kernel_launch(void* const* d_in, const int* in_sizes, int n_in,
                              void* d_out, int out_size)
{
    const float* x_self = (const float*)d_in[0];
    const float* x_nb   = (const float*)d_in[1];
    const float* deg    = (const float*)d_in[2];
    const float* W      = (const float*)d_in[3];
    const float* bias   = (const float*)d_in[4];
    const float* phi    = (const float*)d_in[5];
    const float* w1     = (const float*)d_in[6];
    const float* b1     = (const float*)d_in[7];
    const float* w2     = (const float*)d_in[8];
    const float* b2     = (const float*)d_in[9];
    const float* wsp    = (const float*)d_in[10];
    const float* wnp    = (const float*)d_in[11];
    float* out = (float*)d_out;

    cudaFuncSetAttribute(out_kernel, cudaFuncAttributeMaxDynamicSharedMemorySize, SMEM_TOTAL);

    init_kernel<<<146, 256>>>(w1, b1, w2, b2, W, bias, phi);
    stream_kernel<<<NN / (2 * PAIRS), 256>>>(x_self, x_nb, deg, wsp, wnp);
    out_kernel<<<(NN + 127) / 128, 256, SMEM_TOTAL>>>(bias, out);
}

// round 17
// speedup vs baseline: 1.1264x; 1.0175x over previous
#include <cuda_runtime.h>
#include <cuda_fp16.h>
#include <cstdint>

#define NN 20000
#define KNB 32
#define DD 128
#define GT 4096
#define PAIRS 8            // node-pairs per K2 CTA

// ---------------- device scratch (no runtime allocation) --------------------
__device__ float g_gate_table[GT + 1];
__device__ __align__(16) __half g_Wh[128 * 144];  // fp16 W image, [n][k-interleaved], 288B rows
__device__ __align__(16) float g_u[DD];           // W @ phi_n
__device__ __align__(16) float g_v[DD];           // W @ phi_s
__device__ float g_c0, g_c1;                      // b.phi_n, b.phi_s
__device__ __align__(16) float g_z[NN * DD];      // ws*x_self + wn*y
__device__ float g_beta[NN];                      // ws + wn*gs

// ---------------- K3 smem layout (bytes) — proven R6-R15 GEMM ---------------
#define A_STRIDE_F 40
#define A_BUF_B   20480
#define W_OFF_B   40960
#define EP_OFF_B  77824
#define SMEM_TOTAL 83008

// ---------------- K2 static smem (float offsets) -----------------------------
#define PN_O   0            // 8 warps x 2 nodes x 32 lanes x float4 = 2048
#define SC_O   2048         // 64 raw scores
#define SSP_O  2112         // 8 per-warp s_self partials
#define ATT_O  2120         // 64 att*gate
#define K2_FLOATS 2184

// ---------------- helpers ----------------------------------------------------
__device__ __forceinline__ uint32_t s2u(const void* p) {
    return (uint32_t)__cvta_generic_to_shared(p);
}
__device__ __forceinline__ void cp16p(uint32_t sa, const float* g, bool v) {
    int sz = v ? 16 : 0;
    asm volatile("cp.async.cg.shared.global [%0], [%1], 16, %2;" :: "r"(sa), "l"(g), "r"(sz));
}
#define CP_COMMIT() asm volatile("cp.async.commit_group;" ::: "memory")
#define CP_WAIT1()  asm volatile("cp.async.wait_group 1;" ::: "memory")
#define CP_WAIT0()  asm volatile("cp.async.wait_group 0;" ::: "memory")

__device__ __forceinline__ void mma16(float* c, const uint32_t* a, uint32_t b0, uint32_t b1) {
    asm volatile(
        "mma.sync.aligned.m16n8k16.row.col.f32.f16.f16.f32 "
        "{%0,%1,%2,%3}, {%4,%5,%6,%7}, {%8,%9}, {%0,%1,%2,%3};\n"
        : "+f"(c[0]), "+f"(c[1]), "+f"(c[2]), "+f"(c[3])
        : "r"(a[0]), "r"(a[1]), "r"(a[2]), "r"(a[3]), "r"(b0), "r"(b1));
}
__device__ __forceinline__ uint32_t pack2(float lo, float hi) {
    __half2 h = __floats2half2_rn(lo, hi);
    return *(uint32_t*)&h;
}

// ---------------- K3 GEMM machinery (proven R6-R15) --------------------------
__device__ __forceinline__ void stageA(uint32_t smem_base, int buf,
                                       const float* __restrict__ Ag, int valid) {
    const int t = threadIdx.x;
    const uint32_t base = smem_base + buf * A_BUF_B;
    #pragma unroll
    for (int i = 0; i < 4; i++) {
        int e = t + i * 256;
        int row = e >> 3, c4 = (e & 7) << 2;
        cp16p(base + row * 160 + c4 * 4, Ag + row * DD + c4, row < valid);
    }
}

__device__ __forceinline__ void compute_chunk(
    const float* __restrict__ As, const char* __restrict__ Wb, int kc,
    float (&acc)[2][8][4], int wm, int wn, int lane)
{
    const int q2 = (lane & 3) * 2;
    const int lr = lane >> 2;
    const int r0 = wm * 32 + lr;
    #pragma unroll
    for (int s = 0; s < 2; s++) {
        const int kk = s * 16;
        float2 A00 = *(const float2*)(As + (r0     ) * A_STRIDE_F + kk + q2);
        float2 A01 = *(const float2*)(As + (r0 +  8) * A_STRIDE_F + kk + q2);
        float2 A02 = *(const float2*)(As + (r0     ) * A_STRIDE_F + kk + q2 + 8);
        float2 A03 = *(const float2*)(As + (r0 +  8) * A_STRIDE_F + kk + q2 + 8);
        float2 A10 = *(const float2*)(As + (r0 + 16) * A_STRIDE_F + kk + q2);
        float2 A11 = *(const float2*)(As + (r0 + 24) * A_STRIDE_F + kk + q2);
        float2 A12 = *(const float2*)(As + (r0 + 16) * A_STRIDE_F + kk + q2 + 8);
        float2 A13 = *(const float2*)(As + (r0 + 24) * A_STRIDE_F + kk + q2 + 8);
        uint32_t a0[4], a1[4];
        a0[0] = pack2(A00.x, A00.y); a0[1] = pack2(A01.x, A01.y);
        a0[2] = pack2(A02.x, A02.y); a0[3] = pack2(A03.x, A03.y);
        a1[0] = pack2(A10.x, A10.y); a1[1] = pack2(A11.x, A11.y);
        a1[2] = pack2(A12.x, A12.y); a1[3] = pack2(A13.x, A13.y);
        const int coff = (kc * 2 + s) * 32 + q2 * 4;
        #pragma unroll
        for (int nt = 0; nt < 8; nt++) {
            const int n = wn * 64 + nt * 8 + lr;
            uint2 b = *(const uint2*)(Wb + n * 288 + coff);
            mma16(acc[0][nt], a0, b.x, b.y);
            mma16(acc[1][nt], a1, b.x, b.y);
        }
    }
}

__device__ __forceinline__ void gemm_pipe(
    char* smc, uint32_t smem_base, const float* __restrict__ Abase, int valid,
    float (&acc)[2][8][4], int wm, int wn, int lane)
{
    const int t = threadIdx.x;
    #pragma unroll
    for (int i = 0; i < 9; i++) {
        int e = t + i * 256;
        cp16p(smem_base + W_OFF_B + e * 16,
              (const float*)((const char*)g_Wh + e * 16), true);
    }
    stageA(smem_base, 0, Abase, valid);
    CP_COMMIT();

    const char* Wb = smc + W_OFF_B;
    #pragma unroll
    for (int kc = 0; kc < 4; kc++) {
        if (kc < 3) {
            stageA(smem_base, (kc + 1) & 1, Abase + (kc + 1) * 32, valid);
            CP_COMMIT();
            CP_WAIT1();
        } else {
            CP_WAIT0();
        }
        __syncthreads();
        compute_chunk((const float*)(smc + (kc & 1) * A_BUF_B), Wb, kc,
                      acc, wm, wn, lane);
        __syncthreads();
    }
}

// ---------------- K1: init — one wave ----------------------------------------
// blocks 0..128: gate table (warp does 4 entries); 129..144: W image; 145: u/v/c
__global__ void __launch_bounds__(256) init_kernel(
    const float* __restrict__ w1, const float* __restrict__ b1,
    const float* __restrict__ w2, const float* __restrict__ b2,
    const float* __restrict__ W, const float* __restrict__ bias,
    const float* __restrict__ phi)
{
    const int t = threadIdx.x, lane = t & 31, w = t >> 5;
    const int bx = blockIdx.x;

    if (bx <= 128) {
        const float w1l = w1[lane], w2l = w2[lane];
        const float b1v = b1[0], b2v = b2[0];
        #pragma unroll
        for (int e = 0; e < 4; e++) {
            const int gw = (bx * 8 + w) * 4 + e;
            if (gw <= GT) {
                float d = (float)gw * (64.0f / (float)GT);
                float s = 1.0f / (1.0f + __expf(-(d * w1l + b1v)));
                float p = s * w2l;
                #pragma unroll
                for (int off = 16; off; off >>= 1)
                    p += __shfl_xor_sync(0xffffffffu, p, off);
                if (lane == 0)
                    g_gate_table[gw] = 1.0f / (1.0f + __expf(-(p + b2v)));
            }
        }
    } else if (bx <= 144) {
        const int gid2 = (bx - 129) * 256 + t;
        {
            int n = gid2 >> 5, c = (gid2 >> 2) & 7, q = gid2 & 3;
            int k0 = c * 16 + q * 2;
            __half2 h0 = __floats2half2_rn(W[k0 * DD + n],       W[(k0 + 1) * DD + n]);
            __half2 h1 = __floats2half2_rn(W[(k0 + 8) * DD + n], W[(k0 + 9) * DD + n]);
            *(__half2*)(g_Wh + n * 144 + c * 16 + q * 4)     = h0;
            *(__half2*)(g_Wh + n * 144 + c * 16 + q * 4 + 2) = h1;
        }
        if (gid2 < 1024) {
            int n = gid2 >> 3, j = gid2 & 7;
            *(uint32_t*)(g_Wh + n * 144 + 128 + j * 2) = 0;
        }
    } else {
        float pn0 = phi[lane], pn1 = phi[lane + 32], pn2 = phi[lane + 64], pn3 = phi[lane + 96];
        float ps0 = phi[DD + lane], ps1 = phi[DD + lane + 32];
        float ps2 = phi[DD + lane + 64], ps3 = phi[DD + lane + 96];
        #pragma unroll
        for (int rr = 0; rr < 16; rr++) {
            const int r = w * 16 + rr;
            float w0 = W[r * DD + lane],      w1v = W[r * DD + lane + 32];
            float w2v = W[r * DD + lane + 64], w3 = W[r * DD + lane + 96];
            float pu = w0 * pn0 + w1v * pn1 + w2v * pn2 + w3 * pn3;
            float pv = w0 * ps0 + w1v * ps1 + w2v * ps2 + w3 * ps3;
            #pragma unroll
            for (int off = 16; off; off >>= 1) {
                pu += __shfl_xor_sync(0xffffffffu, pu, off);
                pv += __shfl_xor_sync(0xffffffffu, pv, off);
            }
            if (lane == 0) { g_u[r] = pu; g_v[r] = pv; }
        }
        if (w < 2) {
            float b0 = bias[lane], b1v = bias[lane + 32];
            float b2v = bias[lane + 64], b3 = bias[lane + 96];
            float p = (w == 0)
                ? (b0 * pn0 + b1v * pn1 + b2v * pn2 + b3 * pn3)
                : (b0 * ps0 + b1v * ps1 + b2v * ps2 + b3 * ps3);
            #pragma unroll
            for (int off = 16; off; off >>= 1)
                p += __shfl_xor_sync(0xffffffffu, p, off);
            if (lane == 0) { if (w == 0) g_c0 = p; else g_c1 = p; }
        }
    }
}

// ---------------- K2: register-direct streaming attention, 3 CTAs/SM ---------
// Identical to R15 (passing, 79.9us) except PAIRS 4 -> 8.
// NO cp.async (toolchain constraint).
__global__ void __launch_bounds__(256, 3) stream_kernel(
    const float* __restrict__ x_self, const float* __restrict__ x_nb,
    const float* __restrict__ deg,
    const float* __restrict__ wsp, const float* __restrict__ wnp)
{
    __shared__ float smf[K2_FLOATS];
    const int t = threadIdx.x, lane = t & 31, w = t >> 5;
    const int pair0 = blockIdx.x * PAIRS;
    const int node_t = t >> 7, col_t = t & 127;

    const float4 u4 = *(const float4*)(g_u + lane * 4);
    const float vv = g_v[col_t];
    const float wsv = wsp[0], wnv = wnp[0];
    const float c0 = g_c0, c1 = g_c1;

    float4 rx[8], nx[4];
    float rxs_c, rxs_n = 0.f;

    // prologue: tile 0 full
    {
        const float4* Ab4 = (const float4*)(x_nb + (size_t)pair0 * 2 * KNB * DD);
        #pragma unroll
        for (int i = 0; i < 8; i++)
            rx[i] = Ab4[(w + 8 * i) * 32 + lane];
        rxs_c = x_self[(size_t)(pair0 * 2 + node_t) * DD + col_t];
    }

    #pragma unroll
    for (int it = 0; it < PAIRS; it++) {
        const int node0 = (pair0 + it) * 2;

        // current deg (softmax use; score phase covers latency)
        const float rdg = (w < 2) ? deg[(size_t)node0 * KNB + w * 32 + lane] : 0.f;

        // prefetch first half of next tile
        if (it + 1 < PAIRS) {
            const float4* Ab4 = (const float4*)(x_nb + (size_t)(node0 + 2) * KNB * DD);
            #pragma unroll
            for (int i = 0; i < 4; i++)
                nx[i] = Ab4[(w + 8 * i) * 32 + lane];
            rxs_n = x_self[(size_t)(node0 + 2 + node_t) * DD + col_t];
        }

        // ---- score partials from registers ----
        float v[8];
        #pragma unroll
        for (int i = 0; i < 8; i++) {
            float4 x = rx[i];
            v[i] = x.x * u4.x + x.y * u4.y + x.z * u4.z + x.w * u4.w;
        }
        #pragma unroll
        for (int j = 0; j < 4; j++) {
            float give = (lane & 16) ? v[j] : v[j + 4];
            float keep = (lane & 16) ? v[j + 4] : v[j];
            v[j] = keep + __shfl_xor_sync(0xffffffffu, give, 16);
        }
        #pragma unroll
        for (int j = 0; j < 2; j++) {
            float give = (lane & 8) ? v[j] : v[j + 2];
            float keep = (lane & 8) ? v[j + 2] : v[j];
            v[j] = keep + __shfl_xor_sync(0xffffffffu, give, 8);
        }
        {
            float give = (lane & 4) ? v[0] : v[1];
            float keep = (lane & 4) ? v[1] : v[0];
            v[0] = keep + __shfl_xor_sync(0xffffffffu, give, 4);
        }
        v[0] += __shfl_xor_sync(0xffffffffu, v[0], 2);
        v[0] += __shfl_xor_sync(0xffffffffu, v[0], 1);
        if ((lane & 3) == 0) smf[SC_O + w + 8 * (lane >> 2)] = v[0];

        // ---- s_self partial ----
        {
            float p = rxs_c * vv;
            #pragma unroll
            for (int off = 16; off; off >>= 1)
                p += __shfl_xor_sync(0xffffffffu, p, off);
            if (lane == 0) smf[SSP_O + w] = p;
        }
        __syncthreads();

        // ---- leaky + softmax + gate (warp per node) ----
        if (w < 2) {
            float ssl = smf[SSP_O + w * 4] + smf[SSP_O + w * 4 + 1]
                      + smf[SSP_O + w * 4 + 2] + smf[SSP_O + w * 4 + 3];
            float s = smf[SC_O + w * 32 + lane] + c0 + ssl + c1;
            s = (s > 0.f) ? s : 0.2f * s;
            float m = s;
            #pragma unroll
            for (int off = 16; off; off >>= 1)
                m = fmaxf(m, __shfl_xor_sync(0xffffffffu, m, off));
            float e = __expf(s - m);
            float ss = e;
            #pragma unroll
            for (int off = 16; off; off >>= 1)
                ss += __shfl_xor_sync(0xffffffffu, ss, off);
            float u = fminf(fmaxf(rdg * ((float)GT / 64.0f), 0.0f), (float)GT - 0.001f);
            int ix = (int)u; float fr = u - (float)ix;
            float g0 = g_gate_table[ix];
            float gt = g0 + (g_gate_table[ix + 1] - g0) * fr;
            float a = (e / ss) * gt;
            smf[ATT_O + w * 32 + lane] = a;
            float gs = a;
            #pragma unroll
            for (int off = 16; off; off >>= 1)
                gs += __shfl_xor_sync(0xffffffffu, gs, off);
            if (lane == 0) g_beta[node0 + w] = wsv + wnv * gs;
        }
        __syncthreads();

        // ---- weighted-sum partials from registers (att via broadcast LDS) ----
        {
            float4 pn0 = make_float4(0.f, 0.f, 0.f, 0.f);
            float4 pn1 = make_float4(0.f, 0.f, 0.f, 0.f);
            #pragma unroll
            for (int i = 0; i < 4; i++) {
                float a = smf[ATT_O + w + 8 * i];
                float4 x = rx[i];
                pn0.x += a * x.x; pn0.y += a * x.y; pn0.z += a * x.z; pn0.w += a * x.w;
            }
            #pragma unroll
            for (int i = 4; i < 8; i++) {
                float a = smf[ATT_O + w + 8 * i];
                float4 x = rx[i];
                pn1.x += a * x.x; pn1.y += a * x.y; pn1.z += a * x.z; pn1.w += a * x.w;
            }
            *(float4*)(smf + PN_O + (w * 64 + lane) * 4)      = pn0;
            *(float4*)(smf + PN_O + (w * 64 + 32 + lane) * 4) = pn1;
        }
        __syncthreads();

        // ---- final: sum 8 warp-partials, write z ----
        {
            float y = 0.f;
            #pragma unroll
            for (int ww = 0; ww < 8; ww++)
                y += smf[PN_O + ww * 256 + node_t * 128 + col_t];
            float z = wsv * rxs_c + wnv * y;
            g_z[(size_t)(node0 + node_t) * DD + col_t] = z;
        }

        // ---- rotate + second-half prefetch (covered by z write + next score) --
        if (it + 1 < PAIRS) {
            const float4* Ab4 = (const float4*)(x_nb + (size_t)(node0 + 2) * KNB * DD);
            rx[0] = nx[0]; rx[1] = nx[1]; rx[2] = nx[2]; rx[3] = nx[3];
            #pragma unroll
            for (int i = 4; i < 8; i++)
                rx[i] = Ab4[(w + 8 * i) * 32 + lane];
            rxs_c = rxs_n;
        }
        // barrier-free smem reuse proven in R13 (PN/SC/ATT write-read chains
        // separated by the three per-iteration barriers).
    }
}

// ---------------- K3: out = relu(z @ W + beta_n * b) -------------------------
__global__ void __launch_bounds__(256, 2) out_kernel(
    const float* __restrict__ bias, float* __restrict__ out)
{
    extern __shared__ char smc[];
    const uint32_t smem_base = s2u(smc);
    float* smf = (float*)(smc + EP_OFF_B);
    const int t = threadIdx.x, lane = t & 31, wid = t >> 5;
    const int wm = wid & 3, wn = wid >> 2, la = lane & 3, lr = lane >> 2;
    float* bias_s = smf;
    float* beta_s = smf + 128;

    const int row_base = blockIdx.x * 128;
    int valid = NN - row_base; if (valid > 128) valid = 128;

    if (t < 128) {
        bias_s[t] = bias[t];
        int gr = row_base + t;
        beta_s[t] = (gr < NN) ? g_beta[gr] : 0.f;
    }

    float acc[2][8][4] = {};
    gemm_pipe(smc, smem_base, g_z + (size_t)row_base * DD, valid, acc, wm, wn, lane);

    const int r = wm * 32 + lr;
    const float be0 = beta_s[r], be1 = beta_s[r + 8];
    const float be2 = beta_s[r + 16], be3 = beta_s[r + 24];
    #pragma unroll
    for (int nt = 0; nt < 8; nt++) {
        const int c = wn * 64 + nt * 8 + la * 2;
        const float b0 = bias_s[c], b1 = bias_s[c + 1];
        float o00 = acc[0][nt][0] + be0 * b0, o01 = acc[0][nt][1] + be0 * b1;
        float o10 = acc[0][nt][2] + be1 * b0, o11 = acc[0][nt][3] + be1 * b1;
        float o20 = acc[1][nt][0] + be2 * b0, o21 = acc[1][nt][1] + be2 * b1;
        float o30 = acc[1][nt][2] + be3 * b0, o31 = acc[1][nt][3] + be3 * b1;
        o00 = o00 > 0.f ? o00 : 0.f;  o01 = o01 > 0.f ? o01 : 0.f;
        o10 = o10 > 0.f ? o10 : 0.f;  o11 = o11 > 0.f ? o11 : 0.f;
        o20 = o20 > 0.f ? o20 : 0.f;  o21 = o21 > 0.f ? o21 : 0.f;
        o30 = o30 > 0.f ? o30 : 0.f;  o31 = o31 > 0.f ? o31 : 0.f;
        if (r      < valid) *(float2*)(out + (size_t)(row_base + r     ) * DD + c) = make_float2(o00, o01);
        if (r + 8  < valid) *(float2*)(out + (size_t)(row_base + r + 8 ) * DD + c) = make_float2(o10, o11);
        if (r + 16 < valid) *(float2*)(out + (size_t)(row_base + r + 16) * DD + c) = make_float2(o20, o21);
        if (r + 24 < valid) *(float2*)(out + (size_t)(row_base + r + 24) * DD + c) = make_float2(o30, o31);
    }
}

// ---------------- launch -----------------------------------------------------
extern "C" void kernel_launch(void* const* d_in, const int* in_sizes, int n_in,
                              void* d_out, int out_size)
{
    const float* x_self = (const float*)d_in[0];
    const float* x_nb   = (const float*)d_in[1];
    const float* deg    = (const float*)d_in[2];
    const float* W      = (const float*)d_in[3];
    const float* bias   = (const float*)d_in[4];
    const float* phi    = (const float*)d_in[5];
    const float* w1     = (const float*)d_in[6];
    const float* b1     = (const float*)d_in[7];
    const float* w2     = (const float*)d_in[8];
    const float* b2     = (const float*)d_in[9];
    const float* wsp    = (const float*)d_in[10];
    const float* wnp    = (const float*)d_in[11];
    float* out = (float*)d_out;

    cudaFuncSetAttribute(out_kernel, cudaFuncAttributeMaxDynamicSharedMemorySize, SMEM_TOTAL);

    init_kernel<<<146, 256>>>(w1, b1, w2, b2, W, bias, phi);
    stream_kernel<<<NN / (2 * PAIRS), 256>>>(x_self, x_nb, deg, wsp, wnp);
    out_kernel<<<(NN + 127) / 128, 256, SMEM_TOTAL>>>(bias, out);
}